// round 7
// baseline (speedup 1.0000x reference)
#include <cuda_runtime.h>
#include <cstdint>

#define EPS_ 0.001f

// Problem constants
#define NB   16
#define CIN  64
#define CO   64
#define TT   64
#define VV   384
#define PP   (TT*VV)          // 24576 positions per (n, channel)
#define XP_ELEMS  (NB*CO*PP)  // 25165824
#define CS_ELEMS  (NB*CO*VV)  // 393216

typedef unsigned long long ull;

// Scratch (no cudaMalloc allowed)
__device__ float g_xp[XP_ELEMS];
__device__ float g_colsum[CS_ELEMS];

// ---------------------------------------------------------------------------
// packed f32x2 helpers
// ---------------------------------------------------------------------------
__device__ __forceinline__ ull pack2(float lo, float hi) {
    ull r; asm("mov.b64 %0, {%1, %2};" : "=l"(r) : "f"(lo), "f"(hi)); return r;
}
__device__ __forceinline__ ull splat2(float v) {
    ull r; asm("mov.b64 %0, {%1, %1};" : "=l"(r) : "f"(v)); return r;
}
__device__ __forceinline__ void unpack2(ull p, float& lo, float& hi) {
    asm("mov.b64 {%0, %1}, %2;" : "=f"(lo), "=f"(hi) : "l"(p));
}
__device__ __forceinline__ ull fma2(ull a, ull b, ull c) {
    ull d; asm("fma.rn.f32x2 %0, %1, %2, %3;" : "=l"(d) : "l"(a), "l"(b), "l"(c)); return d;
}

// ---------------------------------------------------------------------------
// mbarrier helpers
// ---------------------------------------------------------------------------
__device__ __forceinline__ uint32_t smem_u32(const void* p) {
    uint32_t a;
    asm("{ .reg .u64 t; cvta.to.shared.u64 t, %1; cvt.u32.u64 %0, t; }" : "=r"(a) : "l"(p));
    return a;
}
__device__ __forceinline__ void mbar_init(uint32_t a, uint32_t cnt) {
    asm volatile("mbarrier.init.shared.b64 [%0], %1;" :: "r"(a), "r"(cnt) : "memory");
}
__device__ __forceinline__ void mbar_arrive(uint32_t a) {
    asm volatile("mbarrier.arrive.shared.b64 _, [%0];" :: "r"(a) : "memory");
}
__device__ __forceinline__ void mbar_wait(uint32_t a, uint32_t parity) {
    uint32_t done;
    asm volatile(
        "{\n\t.reg .pred p;\n\t"
        "mbarrier.try_wait.parity.shared.b64 p, [%1], %2;\n\t"
        "selp.b32 %0, 1, 0, p;\n\t}"
        : "=r"(done) : "r"(a), "r"(parity) : "memory");
    if (!done) {
        asm volatile(
            "{\n\t.reg .pred P1;\n\t"
            "WL_%=:\n\t"
            "mbarrier.try_wait.parity.shared.b64 P1, [%0], %1;\n\t"
            "@P1 bra.uni WD_%=;\n\t"
            "bra.uni WL_%=;\n\t"
            "WD_%=:\n\t}"
            :: "r"(a), "r"(parity) : "memory");
    }
}

// ---------------------------------------------------------------------------
// K0: zero the column-sum accumulator
// ---------------------------------------------------------------------------
__global__ void zero_colsum_kernel() {
    int i = blockIdx.x * blockDim.x + threadIdx.x;
    if (i < CS_ELEMS) g_colsum[i] = 0.0f;
}

// ---------------------------------------------------------------------------
// K1: x'[n,o,p] = sum_c conv_w[o,c] * x[n,c,p] + conv_b[o]
// ---------------------------------------------------------------------------
__global__ __launch_bounds__(256) void conv_kernel(const float* __restrict__ x,
                                                   const float* __restrict__ w,
                                                   const float* __restrict__ b) {
    __shared__ float sW[64 * 65];
    __shared__ float sX[64 * 128];
    const int n   = blockIdx.y;
    const int p0  = blockIdx.x * 128;
    const int tid = threadIdx.x;

    for (int i = tid; i < 4096; i += 256)
        sW[(i >> 6) * 65 + (i & 63)] = w[i];

    const float* xb = x + n * CIN * PP;
    #pragma unroll
    for (int r = 0; r < 8; r++) {
        int idx = tid + 256 * r;
        int c = idx >> 5, p4 = idx & 31;
        ((float4*)sX)[c * 32 + p4] = *((const float4*)(xb + c * PP + p0) + p4);
    }
    __syncthreads();

    const int ob = tid >> 4;
    const int px = tid & 15;
    ull acc2[4][4];
    #pragma unroll
    for (int i = 0; i < 4; i++)
        #pragma unroll
        for (int j = 0; j < 4; j++) acc2[i][j] = 0ull;

    #pragma unroll 8
    for (int c = 0; c < 64; c++) {
        ull xv[4];
        #pragma unroll
        for (int j = 0; j < 4; j++) xv[j] = *(const ull*)&sX[c * 128 + 2 * px + 32 * j];
        ull wv[4];
        #pragma unroll
        for (int i = 0; i < 4; i++) wv[i] = splat2(sW[(ob + 16 * i) * 65 + c]);
        #pragma unroll
        for (int i = 0; i < 4; i++)
            #pragma unroll
            for (int j = 0; j < 4; j++) acc2[i][j] = fma2(wv[i], xv[j], acc2[i][j]);
    }

    #pragma unroll
    for (int i = 0; i < 4; i++) {
        int o = ob + 16 * i;
        float bo = __ldg(&b[o]);
        float* op = g_xp + (n * CO + o) * PP + p0;
        #pragma unroll
        for (int j = 0; j < 4; j++) {
            float lo, hi; unpack2(acc2[i][j], lo, hi);
            float2 o2; o2.x = lo + bo; o2.y = hi + bo;
            *(float2*)&op[2 * px + 32 * j] = o2;
        }
    }
}

// ---------------------------------------------------------------------------
// K2: MLP 7->16->32->64 (ReLU each stage), mask multiply -> Am + colsum.
// (unchanged)
// ---------------------------------------------------------------------------
#define S2_A    0
#define S2_H2   4096
#define S2_W1T  20480
#define S2_B1   20608
#define S2_W2T  20624
#define S2_B2   21136
#define S2_W3T  21168
#define S2_B3   23216
#define S2_FLOATS 23280
#define S2_BYTES  (S2_FLOATS * 4)

__global__ __launch_bounds__(256, 2) void mlp_kernel(
    const float* __restrict__ A,
    const float* __restrict__ w1, const float* __restrict__ b1,
    const float* __restrict__ w2, const float* __restrict__ b2,
    const float* __restrict__ w3, const float* __restrict__ b3,
    float* __restrict__ Am)
{
    extern __shared__ float s[];
    float* sA   = s + S2_A;
    float* sH2  = s + S2_H2;
    float* sW1t = s + S2_W1T; float* sB1 = s + S2_B1;
    float* sW2t = s + S2_W2T; float* sB2 = s + S2_B2;
    float* sW3t = s + S2_W3T; float* sB3 = s + S2_B3;

    const int tid = threadIdx.x;
    const int w0  = blockIdx.x * 32;
    const int v0  = blockIdx.y * 16;
    const int n   = blockIdx.z;

    if (tid < 112) { int c = tid / 7, k = tid % 7; sW1t[k * 16 + c] = w1[tid]; }
    if (tid < 16)  sB1[tid] = b1[tid];
    for (int i = tid; i < 512; i += 256)  { int c = i >> 4, k = i & 15; sW2t[k * 32 + c] = w2[i]; }
    if (tid < 32)  sB2[tid] = b2[tid];
    for (int i = tid; i < 2048; i += 256) { int c = i >> 5, k = i & 31; sW3t[k * 64 + c] = w3[i]; }
    if (tid < 64)  sB3[tid] = b3[tid];

    {
        const int w   = tid & 31;
        const int sub = tid >> 5;
        const float* Ab = A + n * 8 * VV * VV;
        #pragma unroll
        for (int k = 0; k < 8; k++)
            #pragma unroll
            for (int vi = 0; vi < 2; vi++) {
                int v = sub + vi * 8;
                sA[k * 512 + v * 32 + w] = Ab[(k * VV + v0 + v) * VV + w0 + w];
            }
    }
    __syncthreads();

    #pragma unroll
    for (int jj = 0; jj < 2; jj++) {
        const int p = tid + jj * 256;
        float av[7];
        #pragma unroll
        for (int k = 0; k < 7; k++) av[k] = sA[k * 512 + p];

        ull h1p[8];
        #pragma unroll
        for (int ci = 0; ci < 8; ci++) h1p[ci] = *(const ull*)&sB1[2 * ci];
        #pragma unroll
        for (int k = 0; k < 7; k++) {
            ull sv = splat2(av[k]);
            #pragma unroll
            for (int ci = 0; ci < 8; ci++)
                h1p[ci] = fma2(sv, *(const ull*)&sW1t[k * 16 + 2 * ci], h1p[ci]);
        }
        float h1[16];
        #pragma unroll
        for (int ci = 0; ci < 8; ci++) {
            float lo, hi; unpack2(h1p[ci], lo, hi);
            h1[2 * ci]     = fmaxf(lo, 0.0f);
            h1[2 * ci + 1] = fmaxf(hi, 0.0f);
        }

        ull h2p[16];
        #pragma unroll
        for (int ci = 0; ci < 16; ci++) h2p[ci] = *(const ull*)&sB2[2 * ci];
        #pragma unroll
        for (int k = 0; k < 16; k++) {
            ull sv = splat2(h1[k]);
            #pragma unroll
            for (int ci = 0; ci < 16; ci++)
                h2p[ci] = fma2(sv, *(const ull*)&sW2t[k * 32 + 2 * ci], h2p[ci]);
        }
        #pragma unroll
        for (int ci = 0; ci < 16; ci++) {
            float lo, hi; unpack2(h2p[ci], lo, hi);
            sH2[(2 * ci) * 512 + p]     = fmaxf(lo, 0.0f);
            sH2[(2 * ci + 1) * 512 + p] = fmaxf(hi, 0.0f);
        }
    }
    __syncthreads();

    {
        const int w  = tid & 31;
        const int cb = tid >> 5;
        float cs[8];
        #pragma unroll
        for (int i = 0; i < 8; i++) cs[i] = 0.0f;
        ull bp[4];
        #pragma unroll
        for (int ci = 0; ci < 4; ci++) bp[ci] = *(const ull*)&sB3[cb * 8 + 2 * ci];

        #pragma unroll
        for (int pass = 0; pass < 4; pass++) {
            ull acc2[4][4];
            #pragma unroll
            for (int ci = 0; ci < 4; ci++)
                #pragma unroll
                for (int vi = 0; vi < 4; vi++) acc2[ci][vi] = bp[ci];

            #pragma unroll 8
            for (int k = 0; k < 32; k++) {
                ull hs[4];
                #pragma unroll
                for (int vi = 0; vi < 4; vi++)
                    hs[vi] = splat2(sH2[k * 512 + (pass * 4 + vi) * 32 + w]);
                ull wv[4];
                #pragma unroll
                for (int ci = 0; ci < 4; ci++)
                    wv[ci] = *(const ull*)&sW3t[k * 64 + cb * 8 + 2 * ci];
                #pragma unroll
                for (int ci = 0; ci < 4; ci++)
                    #pragma unroll
                    for (int vi = 0; vi < 4; vi++)
                        acc2[ci][vi] = fma2(hs[vi], wv[ci], acc2[ci][vi]);
            }

            #pragma unroll
            for (int vi = 0; vi < 4; vi++) {
                const int v = pass * 4 + vi;
                float m = sA[7 * 512 + v * 32 + w];
                #pragma unroll
                for (int ci = 0; ci < 4; ci++) {
                    float lo, hi; unpack2(acc2[ci][vi], lo, hi);
                    float a0 = fmaxf(lo, 0.0f) * m;
                    float a1 = fmaxf(hi, 0.0f) * m;
                    int c0 = cb * 8 + 2 * ci;
                    Am[((n * CO + c0)     * VV + (v0 + v)) * VV + w0 + w] = a0;
                    Am[((n * CO + c0 + 1) * VV + (v0 + v)) * VV + w0 + w] = a1;
                    cs[2 * ci]     += a0;
                    cs[2 * ci + 1] += a1;
                }
            }
        }
        #pragma unroll
        for (int i = 0; i < 8; i++)
            atomicAdd(&g_colsum[(n * CO + cb * 8 + i) * VV + w0 + w], cs[i]);
    }
}

// ---------------------------------------------------------------------------
// K3: warp-specialized streaming GEMM (An + x' chunks through a 3-stage ring).
// Consumer restructured: w ownership = contiguous quad (4*tx..4*tx+3), An
// loaded once per row as LDS.128, amortized over 8 t-rows (16 fma2 / float4).
// ---------------------------------------------------------------------------
#define BW      128
#define CHUNK_V 32
#define NSTAGE  3
#define STA_FLOATS (CHUNK_V * BW)          // 4096  (An stage)
#define STX_FLOATS (TT * CHUNK_V)          // 2048  (X stage)
#define S3_XOFF    (NSTAGE * STA_FLOATS)   // 12288
#define S3_DYN_FLOATS (NSTAGE * (STA_FLOATS + STX_FLOATS))   // 18432
#define S3_DYN_BYTES  (S3_DYN_FLOATS * 4)                     // 73728

__global__ __launch_bounds__(384, 2) void out_kernel(float* __restrict__ out,
                                                     float* __restrict__ An)
{
    extern __shared__ float s[];
    float* sAn = s;                 // [3][32][128]
    float* sXc = s + S3_XOFF;       // [3][64][32]
    __shared__ float sDl[BW];
    __shared__ __align__(8) ull s_mbar[2 * NSTAGE];

    const int tid = threadIdx.x;
    const int w0  = blockIdx.x * BW;
    const int c   = blockIdx.y;
    const int n   = blockIdx.z;
    const int nc  = n * CO + c;

    const uint32_t mb = smem_u32(s_mbar);
    if (tid == 0) {
        #pragma unroll
        for (int st = 0; st < NSTAGE; st++) {
            mbar_init(mb + st * 8, 128);               // full: 128 producer threads
            mbar_init(mb + (NSTAGE + st) * 8, 8);      // empty: 8 consumer warps
        }
    }
    if (tid < BW) {
        float csv = g_colsum[nc * VV + w0 + tid];
        sDl[tid] = 1.0f / (csv + EPS_);
    }
    __syncthreads();

    float* Anb = An + nc * VV * VV + w0;
    const float* Xb = g_xp + nc * PP;
    const int wid = tid >> 5;

    if (wid >= 8) {
        // ----------------- PRODUCERS (4 warps, 128 threads) -----------------
        const int ptid = tid - 256;   // 0..127
        int stage = 0, ph = 1;
        for (int kc = 0; kc < 12; kc++) {
            float4 curA[8];
            #pragma unroll
            for (int q = 0; q < 8; q++) {
                int idx = ptid + 128 * q;
                int row = idx >> 5, c4 = idx & 31;
                curA[q] = *((const float4*)(Anb + (kc * CHUNK_V + row) * VV) + c4);
            }
            float4 curX[4];
            #pragma unroll
            for (int q = 0; q < 4; q++) {
                int idx = ptid + 128 * q;
                int t = idx >> 3, c4 = idx & 7;
                curX[q] = *((const float4*)(Xb + t * VV + kc * CHUNK_V) + c4);
            }
            mbar_wait(mb + (NSTAGE + stage) * 8, ph);
            float* bufA = sAn + stage * STA_FLOATS;
            float* bufX = sXc + stage * STX_FLOATS;
            #pragma unroll
            for (int q = 0; q < 8; q++) {
                int idx = ptid + 128 * q;
                int row = idx >> 5, c4 = idx & 31;
                ((float4*)bufA)[row * 32 + c4] = curA[q];
                const float4 d4 = ((const float4*)sDl)[c4];
                float4 o4;
                o4.x = curA[q].x * d4.x; o4.y = curA[q].y * d4.y;
                o4.z = curA[q].z * d4.z; o4.w = curA[q].w * d4.w;
                *((float4*)(Anb + (kc * CHUNK_V + row) * VV) + c4) = o4;
            }
            #pragma unroll
            for (int q = 0; q < 4; q++) {
                int idx = ptid + 128 * q;
                int t = idx >> 3, c4 = idx & 7;
                ((float4*)bufX)[t * 8 + c4] = curX[q];
            }
            mbar_arrive(mb + stage * 8);
            if (++stage == NSTAGE) { stage = 0; ph ^= 1; }
        }
    } else {
        // ----------------- CONSUMERS (8 warps, 256 threads) -----------------
        const int tx = tid & 31;      // w quad: 4*tx .. 4*tx+3
        const int wc = wid;           // t rows: wc + 8*i (i=0..7)
        ull acc2[8][2];
        #pragma unroll
        for (int i = 0; i < 8; i++) { acc2[i][0] = 0ull; acc2[i][1] = 0ull; }

        int stage = 0, ph = 0;
        for (int kc = 0; kc < 12; kc++) {
            mbar_wait(mb + stage * 8, ph);
            const float* bufA = sAn + stage * STA_FLOATS;
            const float* bufX = sXc + stage * STX_FLOATS;
            #pragma unroll
            for (int v4 = 0; v4 < 8; v4++) {
                float4 xq[8];
                #pragma unroll
                for (int i = 0; i < 8; i++)
                    xq[i] = *(const float4*)&bufX[(wc + 8 * i) * CHUNK_V + v4 * 4];
                #pragma unroll
                for (int vv = 0; vv < 4; vv++) {
                    const float4 a4 = *(const float4*)&bufA[(v4 * 4 + vv) * BW + 4 * tx];
                    const ull a01 = pack2(a4.x, a4.y);
                    const ull a23 = pack2(a4.z, a4.w);
                    #pragma unroll
                    for (int i = 0; i < 8; i++) {
                        float xs = (vv == 0) ? xq[i].x : (vv == 1) ? xq[i].y
                                 : (vv == 2) ? xq[i].z : xq[i].w;
                        ull sv = splat2(xs);
                        acc2[i][0] = fma2(sv, a01, acc2[i][0]);
                        acc2[i][1] = fma2(sv, a23, acc2[i][1]);
                    }
                }
            }
            if (tx == 0) mbar_arrive(mb + (NSTAGE + stage) * 8);
            if (++stage == NSTAGE) { stage = 0; ph ^= 1; }
        }

        // epilogue: scale by Dl, store out as float4
        const float4 d4 = ((const float4*)sDl)[tx];
        float* ob = out + nc * PP + w0;
        #pragma unroll
        for (int i = 0; i < 8; i++) {
            const int t = wc + 8 * i;
            float l0, h0, l1, h1;
            unpack2(acc2[i][0], l0, h0);
            unpack2(acc2[i][1], l1, h1);
            float4 o;
            o.x = l0 * d4.x; o.y = h0 * d4.y;
            o.z = l1 * d4.z; o.w = h1 * d4.w;
            *(float4*)&ob[t * VV + 4 * tx] = o;
        }
    }
}

// ---------------------------------------------------------------------------
extern "C" void kernel_launch(void* const* d_in, const int* in_sizes, int n_in,
                              void* d_out, int out_size) {
    const float* x      = (const float*)d_in[0];
    const float* A      = (const float*)d_in[1];
    const float* conv_w = (const float*)d_in[2];
    const float* conv_b = (const float*)d_in[3];
    const float* w1     = (const float*)d_in[4];
    const float* b1     = (const float*)d_in[5];
    const float* w2     = (const float*)d_in[6];
    const float* b2     = (const float*)d_in[7];
    const float* w3     = (const float*)d_in[8];
    const float* b3     = (const float*)d_in[9];

    float* out = (float*)d_out;
    float* An  = out + XP_ELEMS;   // tuple layout: out first, then An

    cudaFuncSetAttribute(mlp_kernel, cudaFuncAttributeMaxDynamicSharedMemorySize, S2_BYTES);
    cudaFuncSetAttribute(out_kernel, cudaFuncAttributeMaxDynamicSharedMemorySize, S3_DYN_BYTES);

    zero_colsum_kernel<<<(CS_ELEMS + 255) / 256, 256>>>();
    conv_kernel<<<dim3(PP / 128, NB), 256>>>(x, conv_w, conv_b);
    mlp_kernel<<<dim3(VV / 32, VV / 16, NB), 256, S2_BYTES>>>(A, w1, b1, w2, b2, w3, b3, An);
    out_kernel<<<dim3(VV / BW, CO, NB), 384, S3_DYN_BYTES>>>(out, An);
}